// round 1
// baseline (speedup 1.0000x reference)
#include <cuda_runtime.h>
#include <math.h>

#define NTHREADS 256
#define N 32
#define LDA 33          // padded leading dim -> conflict-free rows AND columns
#define NSWEEP 6
#define EPS 1e-6f
#define NB_BANDS 9
#define T_DIM 128
#define B_DIM 8
#define NITERS 10

struct Rot {
    int   p[16];
    int   q[16];
    float c[16];
    float s[16];
};

// ---------------------------------------------------------------------------
// Cyclic two-sided Jacobi eigendecomposition of symmetric 32x32 in smem.
// On exit: A's diagonal holds eigenvalues, V holds eigenvectors (columns).
// Round-robin tournament ordering: 16 disjoint pairs/round, 31 rounds/sweep.
// ---------------------------------------------------------------------------
__device__ __forceinline__ void jacobi_eigh(float* A, float* V, Rot& rot, int tid)
{
    // V = I
    for (int idx = tid; idx < N * N; idx += NTHREADS) {
        int i = idx >> 5, j = idx & 31;
        V[i * LDA + j] = (i == j) ? 1.0f : 0.0f;
    }
    __syncthreads();

    for (int sweep = 0; sweep < NSWEEP; ++sweep) {
        for (int r = 0; r < N - 1; ++r) {
            // --- phase 1: 16 threads compute rotation angles ---
            if (tid < 16) {
                int p, q;
                if (tid == 0) { p = N - 1; q = r; }
                else {
                    p = (r + tid) % (N - 1);
                    q = (r - tid + (N - 1)) % (N - 1);
                }
                float app = A[p * LDA + p];
                float aqq = A[q * LDA + q];
                float apq = A[p * LDA + q];
                float c, s;
                if (fabsf(apq) > 1e-24f) {
                    float tau = (aqq - app) / (2.0f * apq);
                    float tt  = 1.0f / (fabsf(tau) + sqrtf(1.0f + tau * tau));
                    tt = (tau >= 0.0f) ? tt : -tt;
                    c = rsqrtf(1.0f + tt * tt);
                    s = tt * c;
                } else { c = 1.0f; s = 0.0f; }
                rot.p[tid] = p; rot.q[tid] = q;
                rot.c[tid] = c; rot.s[tid] = s;
            }
            __syncthreads();

            // --- phase 2: row update  A <- J^T A   (512 units, 2 per thread)
#pragma unroll
            for (int h = 0; h < 2; ++h) {
                int u  = tid + h * NTHREADS;
                int pr = u >> 5, j = u & 31;
                int p = rot.p[pr], q = rot.q[pr];
                float c = rot.c[pr], s = rot.s[pr];
                float ap = A[p * LDA + j], aq = A[q * LDA + j];
                A[p * LDA + j] = c * ap - s * aq;
                A[q * LDA + j] = s * ap + c * aq;
            }
            __syncthreads();

            // --- phase 3: col update  A <- A J, and V <- V J
#pragma unroll
            for (int h = 0; h < 2; ++h) {
                int u  = tid + h * NTHREADS;
                int pr = u >> 5, i = u & 31;
                int p = rot.p[pr], q = rot.q[pr];
                float c = rot.c[pr], s = rot.s[pr];
                float ap = A[i * LDA + p], aq = A[i * LDA + q];
                A[i * LDA + p] = c * ap - s * aq;
                A[i * LDA + q] = s * ap + c * aq;
                float vp = V[i * LDA + p], vq = V[i * LDA + q];
                V[i * LDA + p] = c * vp - s * vq;
                V[i * LDA + q] = s * vp + c * vq;
            }
            __syncthreads();
        }
    }
}

// C = A @ B, all smem (LDA-padded). Thread -> (row, 4 cols).
__device__ __forceinline__ void mm_ss(float* C, const float* A, const float* B, int tid)
{
    int r  = tid >> 3;
    int c0 = (tid & 7) << 2;
    float a0 = 0.f, a1 = 0.f, a2 = 0.f, a3 = 0.f;
#pragma unroll 8
    for (int k = 0; k < N; ++k) {
        float a = A[r * LDA + k];
        const float* Bk = B + k * LDA + c0;
        a0 += a * Bk[0]; a1 += a * Bk[1]; a2 += a * Bk[2]; a3 += a * Bk[3];
    }
    float* Cr = C + r * LDA + c0;
    Cr[0] = a0; Cr[1] = a1; Cr[2] = a2; Cr[3] = a3;
    __syncthreads();
}

// C = A(smem) @ B(global, ld=32)
__device__ __forceinline__ void mm_sg(float* C, const float* A,
                                      const float* __restrict__ B, int tid)
{
    int r  = tid >> 3;
    int c0 = (tid & 7) << 2;
    float a0 = 0.f, a1 = 0.f, a2 = 0.f, a3 = 0.f;
#pragma unroll 8
    for (int k = 0; k < N; ++k) {
        float a = A[r * LDA + k];
        const float* Bk = B + k * N + c0;
        a0 += a * Bk[0]; a1 += a * Bk[1]; a2 += a * Bk[2]; a3 += a * Bk[3];
    }
    float* Cr = C + r * LDA + c0;
    Cr[0] = a0; Cr[1] = a1; Cr[2] = a2; Cr[3] = a3;
    __syncthreads();
}

// C1 = V diag(d1) V^T ; C2 = V diag(d2) V^T  (shared pass over V)
__device__ __forceinline__ void recon2(float* C1, float* C2, const float* V,
                                       const float* d1, const float* d2, int tid)
{
    int r  = tid >> 3;
    int c0 = (tid & 7) << 2;
    float x0 = 0.f, x1 = 0.f, x2 = 0.f, x3 = 0.f;
    float y0 = 0.f, y1 = 0.f, y2 = 0.f, y3 = 0.f;
#pragma unroll 8
    for (int k = 0; k < N; ++k) {
        float vr = V[r * LDA + k];
        float w1 = vr * d1[k];
        float w2 = vr * d2[k];
        float v0 = V[(c0 + 0) * LDA + k];
        float v1 = V[(c0 + 1) * LDA + k];
        float v2 = V[(c0 + 2) * LDA + k];
        float v3 = V[(c0 + 3) * LDA + k];
        x0 += w1 * v0; x1 += w1 * v1; x2 += w1 * v2; x3 += w1 * v3;
        y0 += w2 * v0; y1 += w2 * v1; y2 += w2 * v2; y3 += w2 * v3;
    }
    float* C1r = C1 + r * LDA + c0;
    float* C2r = C2 + r * LDA + c0;
    C1r[0] = x0; C1r[1] = x1; C1r[2] = x2; C1r[3] = x3;
    C2r[0] = y0; C2r[1] = y1; C2r[2] = y2; C2r[3] = y3;
    __syncthreads();
}

// C = V diag(d) V^T
__device__ __forceinline__ void recon(float* C, const float* V, const float* d, int tid)
{
    int r  = tid >> 3;
    int c0 = (tid & 7) << 2;
    float x0 = 0.f, x1 = 0.f, x2 = 0.f, x3 = 0.f;
#pragma unroll 8
    for (int k = 0; k < N; ++k) {
        float w = V[r * LDA + k] * d[k];
        x0 += w * V[(c0 + 0) * LDA + k];
        x1 += w * V[(c0 + 1) * LDA + k];
        x2 += w * V[(c0 + 2) * LDA + k];
        x3 += w * V[(c0 + 3) * LDA + k];
    }
    float* Cr = C + r * LDA + c0;
    Cr[0] = x0; Cr[1] = x1; Cr[2] = x2; Cr[3] = x3;
    __syncthreads();
}

// C = (first ? 0 : C) + w * V diag(d) V^T
__device__ __forceinline__ void recon_acc(float* C, const float* V, const float* d,
                                          float w, bool first, int tid)
{
    int r  = tid >> 3;
    int c0 = (tid & 7) << 2;
    float x0 = 0.f, x1 = 0.f, x2 = 0.f, x3 = 0.f;
#pragma unroll 8
    for (int k = 0; k < N; ++k) {
        float wk = V[r * LDA + k] * d[k];
        x0 += wk * V[(c0 + 0) * LDA + k];
        x1 += wk * V[(c0 + 1) * LDA + k];
        x2 += wk * V[(c0 + 2) * LDA + k];
        x3 += wk * V[(c0 + 3) * LDA + k];
    }
    float* Cr = C + r * LDA + c0;
    if (first) {
        Cr[0] = w * x0; Cr[1] = w * x1; Cr[2] = w * x2; Cr[3] = w * x3;
    } else {
        Cr[0] += w * x0; Cr[1] += w * x1; Cr[2] += w * x2; Cr[3] += w * x3;
    }
    __syncthreads();
}

// ---------------------------------------------------------------------------
// One CTA per output site (b, t, band). Full Karcher-mean pipeline in smem.
// ---------------------------------------------------------------------------
__global__ void __launch_bounds__(NTHREADS)
wfm_kernel(const float* __restrict__ x, const float* __restrict__ rw,
           float* __restrict__ out, int K, int t_out)
{
    __shared__ float sMean[N * LDA];
    __shared__ float sV   [N * LDA];
    __shared__ float sMs  [N * LDA];
    __shared__ float sMis [N * LDA];
    __shared__ float sW1  [N * LDA];
    __shared__ float sW2  [N * LDA];
    __shared__ float sTan [N * LDA];
    __shared__ float se1[N], se2[N];
    __shared__ float sw[8];
    __shared__ Rot   rot;

    const int tid = threadIdx.x;
    const int bid = blockIdx.x;
    const int band = bid % NB_BANDS;
    const int tmp  = bid / NB_BANDS;
    const int tt   = tmp % t_out;
    const int b    = tmp / t_out;

    const float* base =
        x + ((size_t)(b * T_DIM + tt) * NB_BANDS + band) * (size_t)(N * N);

    // softmax(raw_weights)
    if (tid == 0) {
        float m = rw[0];
        for (int k = 1; k < K; ++k) m = fmaxf(m, rw[k]);
        float se = 0.f;
        for (int k = 0; k < K; ++k) { float e = __expf(rw[k] - m); sw[k] = e; se += e; }
        float inv = 1.0f / se;
        for (int k = 0; k < K; ++k) sw[k] *= inv;
    }
    __syncthreads();

    // initial mean = sum_k w_k M_k
    for (int idx = tid; idx < N * N; idx += NTHREADS) {
        int i = idx >> 5, j = idx & 31;
        float acc = 0.f;
        for (int k = 0; k < K; ++k)
            acc += sw[k] * base[(size_t)k * NB_BANDS * N * N + idx];
        sMean[i * LDA + j] = acc;
    }
    __syncthreads();

    for (int it = 0; it < NITERS; ++it) {
        // eigh(mean) -> sMean diag destroyed, sV eigenvectors
        jacobi_eigh(sMean, sV, rot, tid);
        if (tid < N) {
            float v  = fmaxf(sMean[tid * LDA + tid], EPS);
            float sv = sqrtf(v);
            se1[tid] = sv;
            se2[tid] = 1.0f / sv;
        }
        __syncthreads();
        recon2(sMs, sMis, sV, se1, se2, tid);   // ms, mis

        // tangent = sum_k w_k log(mis M_k mis)
        for (int k = 0; k < K; ++k) {
            const float* Mk = base + (size_t)k * NB_BANDS * N * N;
            mm_sg(sW1, sMis, Mk, tid);          // W1 = mis @ Mk
            mm_ss(sW2, sW1, sMis, tid);         // W2 = inner (sym)
            jacobi_eigh(sW2, sV, rot, tid);
            if (tid < N) se1[tid] = __logf(fmaxf(sW2[tid * LDA + tid], EPS));
            __syncthreads();
            recon_acc(sTan, sV, se1, sw[k], k == 0, tid);
        }

        // mean = ms @ exp(tangent) @ ms
        jacobi_eigh(sTan, sV, rot, tid);
        if (tid < N) se1[tid] = __expf(sTan[tid * LDA + tid]);
        __syncthreads();
        recon(sW1, sV, se1, tid);               // expT
        mm_ss(sW2, sMs, sW1, tid);
        mm_ss(sMean, sW2, sMs, tid);
    }

    float* o = out + ((size_t)(b * t_out + tt) * NB_BANDS + band) * (size_t)(N * N);
    for (int idx = tid; idx < N * N; idx += NTHREADS)
        o[idx] = sMean[(idx >> 5) * LDA + (idx & 31)];
}

extern "C" void kernel_launch(void* const* d_in, const int* in_sizes, int n_in,
                              void* d_out, int out_size)
{
    const float* x  = (const float*)d_in[0];
    const float* rw = (const float*)d_in[1];
    float* out = (float*)d_out;

    const int K     = in_sizes[1];        // KERNEL_SIZE (=2)
    const int t_out = T_DIM - K + 1;      // 127
    const int nblocks = B_DIM * t_out * NB_BANDS;

    wfm_kernel<<<nblocks, NTHREADS>>>(x, rw, out, K, t_out);
}

// round 2
// speedup vs baseline: 19.9279x; 19.9279x over previous
#include <cuda_runtime.h>
#include <math.h>

#define NTHREADS 256
#define N 32
#define LDA 33          // padded leading dim -> conflict-free rows AND columns
#define NSWEEP 6
#define EPS 1e-6f
#define NB_BANDS 9
#define T_DIM 128
#define B_DIM 8
#define NITERS 10

struct Rot {
    int   p[16];
    int   q[16];
    float c[16];
    float s[16];
};

// ---------------------------------------------------------------------------
// Cyclic two-sided Jacobi eigendecomposition of symmetric 32x32 in smem.
// On exit: A's diagonal holds eigenvalues, V holds eigenvectors (columns).
// ---------------------------------------------------------------------------
__device__ __forceinline__ void jacobi_eigh(float* A, float* V, Rot& rot, int tid)
{
    for (int idx = tid; idx < N * N; idx += NTHREADS) {
        int i = idx >> 5, j = idx & 31;
        V[i * LDA + j] = (i == j) ? 1.0f : 0.0f;
    }
    __syncthreads();

    for (int sweep = 0; sweep < NSWEEP; ++sweep) {
        for (int r = 0; r < N - 1; ++r) {
            if (tid < 16) {
                int p, q;
                if (tid == 0) { p = N - 1; q = r; }
                else {
                    p = (r + tid) % (N - 1);
                    q = (r - tid + (N - 1)) % (N - 1);
                }
                float app = A[p * LDA + p];
                float aqq = A[q * LDA + q];
                float apq = A[p * LDA + q];
                float c, s;
                if (fabsf(apq) > 1e-24f) {
                    float tau = (aqq - app) / (2.0f * apq);
                    float tt  = 1.0f / (fabsf(tau) + sqrtf(1.0f + tau * tau));
                    tt = (tau >= 0.0f) ? tt : -tt;
                    c = rsqrtf(1.0f + tt * tt);
                    s = tt * c;
                } else { c = 1.0f; s = 0.0f; }
                rot.p[tid] = p; rot.q[tid] = q;
                rot.c[tid] = c; rot.s[tid] = s;
            }
            __syncthreads();

#pragma unroll
            for (int h = 0; h < 2; ++h) {
                int u  = tid + h * NTHREADS;
                int pr = u >> 5, j = u & 31;
                int p = rot.p[pr], q = rot.q[pr];
                float c = rot.c[pr], s = rot.s[pr];
                float ap = A[p * LDA + j], aq = A[q * LDA + j];
                A[p * LDA + j] = c * ap - s * aq;
                A[q * LDA + j] = s * ap + c * aq;
            }
            __syncthreads();

#pragma unroll
            for (int h = 0; h < 2; ++h) {
                int u  = tid + h * NTHREADS;
                int pr = u >> 5, i = u & 31;
                int p = rot.p[pr], q = rot.q[pr];
                float c = rot.c[pr], s = rot.s[pr];
                float ap = A[i * LDA + p], aq = A[i * LDA + q];
                A[i * LDA + p] = c * ap - s * aq;
                A[i * LDA + q] = s * ap + c * aq;
                float vp = V[i * LDA + p], vq = V[i * LDA + q];
                V[i * LDA + p] = c * vp - s * vq;
                V[i * LDA + q] = s * vp + c * vq;
            }
            __syncthreads();
        }
    }
}

// C = A @ B, all smem (LDA-padded).
__device__ __forceinline__ void mm_ss(float* C, const float* A, const float* B, int tid)
{
    int r  = tid >> 3;
    int c0 = (tid & 7) << 2;
    float a0 = 0.f, a1 = 0.f, a2 = 0.f, a3 = 0.f;
#pragma unroll 8
    for (int k = 0; k < N; ++k) {
        float a = A[r * LDA + k];
        const float* Bk = B + k * LDA + c0;
        a0 += a * Bk[0]; a1 += a * Bk[1]; a2 += a * Bk[2]; a3 += a * Bk[3];
    }
    float* Cr = C + r * LDA + c0;
    Cr[0] = a0; Cr[1] = a1; Cr[2] = a2; Cr[3] = a3;
    __syncthreads();
}

// C = A(smem) @ B(global, ld=32)
__device__ __forceinline__ void mm_sg(float* C, const float* A,
                                      const float* __restrict__ B, int tid)
{
    int r  = tid >> 3;
    int c0 = (tid & 7) << 2;
    float a0 = 0.f, a1 = 0.f, a2 = 0.f, a3 = 0.f;
#pragma unroll 8
    for (int k = 0; k < N; ++k) {
        float a = A[r * LDA + k];
        const float* Bk = B + k * N + c0;
        a0 += a * Bk[0]; a1 += a * Bk[1]; a2 += a * Bk[2]; a3 += a * Bk[3];
    }
    float* Cr = C + r * LDA + c0;
    Cr[0] = a0; Cr[1] = a1; Cr[2] = a2; Cr[3] = a3;
    __syncthreads();
}

// C1 = V diag(d1) V^T ; C2 = V diag(d2) V^T
__device__ __forceinline__ void recon2(float* C1, float* C2, const float* V,
                                       const float* d1, const float* d2, int tid)
{
    int r  = tid >> 3;
    int c0 = (tid & 7) << 2;
    float x0 = 0.f, x1 = 0.f, x2 = 0.f, x3 = 0.f;
    float y0 = 0.f, y1 = 0.f, y2 = 0.f, y3 = 0.f;
#pragma unroll 8
    for (int k = 0; k < N; ++k) {
        float vr = V[r * LDA + k];
        float w1 = vr * d1[k];
        float w2 = vr * d2[k];
        float v0 = V[(c0 + 0) * LDA + k];
        float v1 = V[(c0 + 1) * LDA + k];
        float v2 = V[(c0 + 2) * LDA + k];
        float v3 = V[(c0 + 3) * LDA + k];
        x0 += w1 * v0; x1 += w1 * v1; x2 += w1 * v2; x3 += w1 * v3;
        y0 += w2 * v0; y1 += w2 * v1; y2 += w2 * v2; y3 += w2 * v3;
    }
    float* C1r = C1 + r * LDA + c0;
    float* C2r = C2 + r * LDA + c0;
    C1r[0] = x0; C1r[1] = x1; C1r[2] = x2; C1r[3] = x3;
    C2r[0] = y0; C2r[1] = y1; C2r[2] = y2; C2r[3] = y3;
    __syncthreads();
}

// C = V diag(d) V^T
__device__ __forceinline__ void recon(float* C, const float* V, const float* d, int tid)
{
    int r  = tid >> 3;
    int c0 = (tid & 7) << 2;
    float x0 = 0.f, x1 = 0.f, x2 = 0.f, x3 = 0.f;
#pragma unroll 8
    for (int k = 0; k < N; ++k) {
        float w = V[r * LDA + k] * d[k];
        x0 += w * V[(c0 + 0) * LDA + k];
        x1 += w * V[(c0 + 1) * LDA + k];
        x2 += w * V[(c0 + 2) * LDA + k];
        x3 += w * V[(c0 + 3) * LDA + k];
    }
    float* Cr = C + r * LDA + c0;
    Cr[0] = x0; Cr[1] = x1; Cr[2] = x2; Cr[3] = x3;
    __syncthreads();
}

// C = (first ? 0 : C) + w * V diag(d) V^T
__device__ __forceinline__ void recon_acc(float* C, const float* V, const float* d,
                                          float w, bool first, int tid)
{
    int r  = tid >> 3;
    int c0 = (tid & 7) << 2;
    float x0 = 0.f, x1 = 0.f, x2 = 0.f, x3 = 0.f;
#pragma unroll 8
    for (int k = 0; k < N; ++k) {
        float wk = V[r * LDA + k] * d[k];
        x0 += wk * V[(c0 + 0) * LDA + k];
        x1 += wk * V[(c0 + 1) * LDA + k];
        x2 += wk * V[(c0 + 2) * LDA + k];
        x3 += wk * V[(c0 + 3) * LDA + k];
    }
    float* Cr = C + r * LDA + c0;
    if (first) {
        Cr[0] = w * x0; Cr[1] = w * x1; Cr[2] = w * x2; Cr[3] = w * x3;
    } else {
        Cr[0] += w * x0; Cr[1] += w * x1; Cr[2] += w * x2; Cr[3] += w * x3;
    }
    __syncthreads();
}

// ---------------------------------------------------------------------------
// One CTA per output site (b, t, band).
// K == 2 : closed-form geodesic point   A^{1/2} (A^{-1/2} B A^{-1/2})^{w2} A^{1/2}
//          (the exact fixed point of the reference's Karcher iteration)
// K != 2 : full iterative Karcher mean (reference replica)
// ---------------------------------------------------------------------------
__global__ void __launch_bounds__(NTHREADS)
wfm_kernel(const float* __restrict__ x, const float* __restrict__ rw,
           float* __restrict__ out, int K, int t_out)
{
    __shared__ float sA  [N * LDA];
    __shared__ float sV  [N * LDA];
    __shared__ float sMs [N * LDA];
    __shared__ float sMis[N * LDA];
    __shared__ float sW1 [N * LDA];
    __shared__ float sW2 [N * LDA];
    __shared__ float sTan[N * LDA];
    __shared__ float se1[N], se2[N];
    __shared__ float sw[8];
    __shared__ Rot   rot;

    const int tid = threadIdx.x;
    const int bid = blockIdx.x;
    const int band = bid % NB_BANDS;
    const int tmp  = bid / NB_BANDS;
    const int tt   = tmp % t_out;
    const int b    = tmp / t_out;

    const float* base =
        x + ((size_t)(b * T_DIM + tt) * NB_BANDS + band) * (size_t)(N * N);

    // softmax(raw_weights)
    if (tid == 0) {
        float m = rw[0];
        for (int k = 1; k < K; ++k) m = fmaxf(m, rw[k]);
        float se = 0.f;
        for (int k = 0; k < K; ++k) { float e = __expf(rw[k] - m); sw[k] = e; se += e; }
        float inv = 1.0f / se;
        for (int k = 0; k < K; ++k) sw[k] *= inv;
    }
    __syncthreads();

    if (K == 2) {
        // ---------------- closed form ----------------
        const float* Ma = base;                                   // x[b, tt]
        const float* Mb = base + (size_t)NB_BANDS * N * N;        // x[b, tt+1]
        const float w2 = sw[1];

        for (int idx = tid; idx < N * N; idx += NTHREADS)
            sA[(idx >> 5) * LDA + (idx & 31)] = Ma[idx];
        __syncthreads();

        jacobi_eigh(sA, sV, rot, tid);                 // A = V diag(l) V^T
        if (tid < N) {
            float v  = fmaxf(sA[tid * LDA + tid], EPS);
            float sv = sqrtf(v);
            se1[tid] = sv;
            se2[tid] = 1.0f / sv;
        }
        __syncthreads();
        recon2(sMs, sMis, sV, se1, se2, tid);          // A^{1/2}, A^{-1/2}

        mm_sg(sW1, sMis, Mb, tid);                     // A^{-1/2} B
        mm_ss(sW2, sW1, sMis, tid);                    // C = A^{-1/2} B A^{-1/2}

        jacobi_eigh(sW2, sV, rot, tid);                // C = V diag(mu) V^T
        if (tid < N)
            se1[tid] = __expf(w2 * __logf(fmaxf(sW2[tid * LDA + tid], EPS)));
        __syncthreads();
        recon(sW1, sV, se1, tid);                      // C^{w2}

        mm_ss(sW2, sMs, sW1, tid);                     // A^{1/2} C^{w2}
        mm_ss(sA, sW2, sMs, tid);                      // result
    } else {
        // ---------------- iterative fallback ----------------
        for (int idx = tid; idx < N * N; idx += NTHREADS) {
            float acc = 0.f;
            for (int k = 0; k < K; ++k)
                acc += sw[k] * base[(size_t)k * NB_BANDS * N * N + idx];
            sA[(idx >> 5) * LDA + (idx & 31)] = acc;
        }
        __syncthreads();

        for (int it = 0; it < NITERS; ++it) {
            jacobi_eigh(sA, sV, rot, tid);
            if (tid < N) {
                float v  = fmaxf(sA[tid * LDA + tid], EPS);
                float sv = sqrtf(v);
                se1[tid] = sv;
                se2[tid] = 1.0f / sv;
            }
            __syncthreads();
            recon2(sMs, sMis, sV, se1, se2, tid);

            for (int k = 0; k < K; ++k) {
                const float* Mk = base + (size_t)k * NB_BANDS * N * N;
                mm_sg(sW1, sMis, Mk, tid);
                mm_ss(sW2, sW1, sMis, tid);
                jacobi_eigh(sW2, sV, rot, tid);
                if (tid < N) se1[tid] = __logf(fmaxf(sW2[tid * LDA + tid], EPS));
                __syncthreads();
                recon_acc(sTan, sV, se1, sw[k], k == 0, tid);
            }

            jacobi_eigh(sTan, sV, rot, tid);
            if (tid < N) se1[tid] = __expf(sTan[tid * LDA + tid]);
            __syncthreads();
            recon(sW1, sV, se1, tid);
            mm_ss(sW2, sMs, sW1, tid);
            mm_ss(sA, sW2, sMs, tid);
        }
    }

    float* o = out + ((size_t)(b * t_out + tt) * NB_BANDS + band) * (size_t)(N * N);
    for (int idx = tid; idx < N * N; idx += NTHREADS)
        o[idx] = sA[(idx >> 5) * LDA + (idx & 31)];
}

extern "C" void kernel_launch(void* const* d_in, const int* in_sizes, int n_in,
                              void* d_out, int out_size)
{
    const float* x  = (const float*)d_in[0];
    const float* rw = (const float*)d_in[1];
    float* out = (float*)d_out;

    const int K     = in_sizes[1];        // KERNEL_SIZE (=2)
    const int t_out = T_DIM - K + 1;      // 127
    const int nblocks = B_DIM * t_out * NB_BANDS;

    wfm_kernel<<<nblocks, NTHREADS>>>(x, rw, out, K, t_out);
}

// round 3
// speedup vs baseline: 24.8950x; 1.2493x over previous
#include <cuda_runtime.h>
#include <math.h>

#define NTHREADS 256
#define N 32
#define LDA 33          // padded leading dim -> conflict-free rows AND columns
#define NSWEEP 6
#define EPS 1e-6f
#define NB_BANDS 9
#define T_DIM 128
#define B_DIM 8
#define NITERS 10

// tournament pair (p,q) for pair-index t in round r
__device__ __forceinline__ void pairpq(int r, int t, int& p, int& q)
{
    if (t == 0) { p = N - 1; q = r; }
    else {
        p = (r + t) % (N - 1);
        q = (r - t + (N - 1)) % (N - 1);
    }
}

__device__ __forceinline__ void rotcs(const float* A, int p, int q, float& c, float& s)
{
    float app = A[p * LDA + p];
    float aqq = A[q * LDA + q];
    float apq = A[p * LDA + q];
    if (fabsf(apq) > 1e-24f) {
        float tau = (aqq - app) / (2.0f * apq);
        float tt  = 1.0f / (fabsf(tau) + sqrtf(1.0f + tau * tau));
        tt = (tau >= 0.0f) ? tt : -tt;
        c = rsqrtf(1.0f + tt * tt);
        s = tt * c;
    } else { c = 1.0f; s = 0.0f; }
}

// ---------------------------------------------------------------------------
// Cyclic two-sided Jacobi eigh, warp-per-pair layout.
// Warp w owns pairs {w, w+8} -> 4 exclusive rows; rotations computed
// redundantly per lane from broadcast reads; 2 block barriers per round.
// On exit: diag(A) = eigenvalues, V columns = eigenvectors.
// ---------------------------------------------------------------------------
__device__ __forceinline__ void jacobi_eigh(float* A, float* V, int tid)
{
    const int wid  = tid >> 5;
    const int lane = tid & 31;

    for (int idx = tid; idx < N * N; idx += NTHREADS) {
        int i = idx >> 5, j = idx & 31;
        V[i * LDA + j] = (i == j) ? 1.0f : 0.0f;
    }
    __syncthreads();

    for (int sweep = 0; sweep < NSWEEP; ++sweep) {
        for (int r = 0; r < N - 1; ++r) {
            int p0, q0, p1, q1;
            pairpq(r, wid,     p0, q0);
            pairpq(r, wid + 8, p1, q1);

            // rotations from this warp's own rows (no cross-warp hazard)
            float c0, s0, c1, s1;
            rotcs(A, p0, q0, c0, s0);
            rotcs(A, p1, q1, c1, s1);
            __syncwarp();

            // row update: A <- J^T A on the 4 rows this warp owns
            {
                float ap = A[p0 * LDA + lane], aq = A[q0 * LDA + lane];
                A[p0 * LDA + lane] = c0 * ap - s0 * aq;
                A[q0 * LDA + lane] = s0 * ap + c0 * aq;
                ap = A[p1 * LDA + lane]; aq = A[q1 * LDA + lane];
                A[p1 * LDA + lane] = c1 * ap - s1 * aq;
                A[q1 * LDA + lane] = s1 * ap + c1 * aq;
            }
            __syncthreads();

            // col update: A <- A J, V <- V J (lane = row index)
            {
                float ap = A[lane * LDA + p0], aq = A[lane * LDA + q0];
                A[lane * LDA + p0] = c0 * ap - s0 * aq;
                A[lane * LDA + q0] = s0 * ap + c0 * aq;
                float vp = V[lane * LDA + p0], vq = V[lane * LDA + q0];
                V[lane * LDA + p0] = c0 * vp - s0 * vq;
                V[lane * LDA + q0] = s0 * vp + c0 * vq;
                ap = A[lane * LDA + p1]; aq = A[lane * LDA + q1];
                A[lane * LDA + p1] = c1 * ap - s1 * aq;
                A[lane * LDA + q1] = s1 * ap + c1 * aq;
                vp = V[lane * LDA + p1]; vq = V[lane * LDA + q1];
                V[lane * LDA + p1] = c1 * vp - s1 * vq;
                V[lane * LDA + q1] = s1 * vp + c1 * vq;
            }
            __syncthreads();
        }
    }
}

// In-place Cholesky (lower). Strict upper left as junk (zeroed separately).
__device__ __forceinline__ void cholesky(float* A, int tid)
{
    for (int k = 0; k < N; ++k) {
        if (tid < 32) {
            float akk = A[k * LDA + k];
            float inv = rsqrtf(fmaxf(akk, 1e-12f));
            float v   = A[tid * LDA + k];
            float res = (tid == k) ? (akk * inv) : (v * inv);
            if (tid >= k) A[tid * LDA + k] = res;
        }
        __syncthreads();
        for (int idx = tid; idx < N * N; idx += NTHREADS) {
            int i = idx >> 5, j = idx & 31;
            if (i > k && j > k && j <= i)
                A[i * LDA + j] -= A[i * LDA + k] * A[j * LDA + k];
        }
        __syncthreads();
    }
}

// W = L^{-1} (lower-tri). Thread c owns column c (no cross-thread deps).
// Meanwhile threads >=32 zero the strict upper of L so it can be used in mm.
__device__ __forceinline__ void trinv_and_cleanL(float* L, float* W, int tid)
{
    if (tid < 32) {
        int c = tid;
        for (int k = 0; k < c; ++k) W[k * LDA + c] = 0.0f;
        for (int k = c; k < N; ++k) {
            float s = (k == c) ? 1.0f : 0.0f;
            for (int j = c; j < k; ++j)
                s -= L[k * LDA + j] * W[j * LDA + c];
            W[k * LDA + c] = s * (1.0f / L[k * LDA + k]);
        }
    } else {
        // zero strict upper of L
        for (int idx = tid - 32; idx < N * N; idx += (NTHREADS - 32)) {
            int i = idx >> 5, j = idx & 31;
            if (j > i) L[i * LDA + j] = 0.0f;
        }
    }
    __syncthreads();
}

// C = A @ B (both smem, LDA-padded)
__device__ __forceinline__ void mm_ss(float* C, const float* A, const float* B, int tid)
{
    int r  = tid >> 3;
    int c0 = (tid & 7) << 2;
    float a0 = 0.f, a1 = 0.f, a2 = 0.f, a3 = 0.f;
#pragma unroll 8
    for (int k = 0; k < N; ++k) {
        float a = A[r * LDA + k];
        const float* Bk = B + k * LDA + c0;
        a0 += a * Bk[0]; a1 += a * Bk[1]; a2 += a * Bk[2]; a3 += a * Bk[3];
    }
    float* Cr = C + r * LDA + c0;
    Cr[0] = a0; Cr[1] = a1; Cr[2] = a2; Cr[3] = a3;
    __syncthreads();
}

// C = A(smem) @ B(global, ld=32)
__device__ __forceinline__ void mm_sg(float* C, const float* A,
                                      const float* __restrict__ B, int tid)
{
    int r  = tid >> 3;
    int c0 = (tid & 7) << 2;
    float a0 = 0.f, a1 = 0.f, a2 = 0.f, a3 = 0.f;
#pragma unroll 8
    for (int k = 0; k < N; ++k) {
        float a = A[r * LDA + k];
        const float* Bk = B + k * N + c0;
        a0 += a * Bk[0]; a1 += a * Bk[1]; a2 += a * Bk[2]; a3 += a * Bk[3];
    }
    float* Cr = C + r * LDA + c0;
    Cr[0] = a0; Cr[1] = a1; Cr[2] = a2; Cr[3] = a3;
    __syncthreads();
}

// C = A @ B^T (both smem)
__device__ __forceinline__ void mm_ss_bt(float* C, const float* A, const float* B, int tid)
{
    int r  = tid >> 3;
    int c0 = (tid & 7) << 2;
    float a0 = 0.f, a1 = 0.f, a2 = 0.f, a3 = 0.f;
#pragma unroll 8
    for (int k = 0; k < N; ++k) {
        float a = A[r * LDA + k];
        a0 += a * B[(c0 + 0) * LDA + k];
        a1 += a * B[(c0 + 1) * LDA + k];
        a2 += a * B[(c0 + 2) * LDA + k];
        a3 += a * B[(c0 + 3) * LDA + k];
    }
    float* Cr = C + r * LDA + c0;
    Cr[0] = a0; Cr[1] = a1; Cr[2] = a2; Cr[3] = a3;
    __syncthreads();
}

// C1 = V diag(d1) V^T ; C2 = V diag(d2) V^T
__device__ __forceinline__ void recon2(float* C1, float* C2, const float* V,
                                       const float* d1, const float* d2, int tid)
{
    int r  = tid >> 3;
    int c0 = (tid & 7) << 2;
    float x0 = 0.f, x1 = 0.f, x2 = 0.f, x3 = 0.f;
    float y0 = 0.f, y1 = 0.f, y2 = 0.f, y3 = 0.f;
#pragma unroll 8
    for (int k = 0; k < N; ++k) {
        float vr = V[r * LDA + k];
        float w1 = vr * d1[k];
        float w2 = vr * d2[k];
        float v0 = V[(c0 + 0) * LDA + k];
        float v1 = V[(c0 + 1) * LDA + k];
        float v2 = V[(c0 + 2) * LDA + k];
        float v3 = V[(c0 + 3) * LDA + k];
        x0 += w1 * v0; x1 += w1 * v1; x2 += w1 * v2; x3 += w1 * v3;
        y0 += w2 * v0; y1 += w2 * v1; y2 += w2 * v2; y3 += w2 * v3;
    }
    float* C1r = C1 + r * LDA + c0;
    float* C2r = C2 + r * LDA + c0;
    C1r[0] = x0; C1r[1] = x1; C1r[2] = x2; C1r[3] = x3;
    C2r[0] = y0; C2r[1] = y1; C2r[2] = y2; C2r[3] = y3;
    __syncthreads();
}

// C = V diag(d) V^T
__device__ __forceinline__ void recon(float* C, const float* V, const float* d, int tid)
{
    int r  = tid >> 3;
    int c0 = (tid & 7) << 2;
    float x0 = 0.f, x1 = 0.f, x2 = 0.f, x3 = 0.f;
#pragma unroll 8
    for (int k = 0; k < N; ++k) {
        float w = V[r * LDA + k] * d[k];
        x0 += w * V[(c0 + 0) * LDA + k];
        x1 += w * V[(c0 + 1) * LDA + k];
        x2 += w * V[(c0 + 2) * LDA + k];
        x3 += w * V[(c0 + 3) * LDA + k];
    }
    float* Cr = C + r * LDA + c0;
    Cr[0] = x0; Cr[1] = x1; Cr[2] = x2; Cr[3] = x3;
    __syncthreads();
}

// C = (first ? 0 : C) + w * V diag(d) V^T
__device__ __forceinline__ void recon_acc(float* C, const float* V, const float* d,
                                          float w, bool first, int tid)
{
    int r  = tid >> 3;
    int c0 = (tid & 7) << 2;
    float x0 = 0.f, x1 = 0.f, x2 = 0.f, x3 = 0.f;
#pragma unroll 8
    for (int k = 0; k < N; ++k) {
        float wk = V[r * LDA + k] * d[k];
        x0 += wk * V[(c0 + 0) * LDA + k];
        x1 += wk * V[(c0 + 1) * LDA + k];
        x2 += wk * V[(c0 + 2) * LDA + k];
        x3 += wk * V[(c0 + 3) * LDA + k];
    }
    float* Cr = C + r * LDA + c0;
    if (first) {
        Cr[0] = w * x0; Cr[1] = w * x1; Cr[2] = w * x2; Cr[3] = w * x3;
    } else {
        Cr[0] += w * x0; Cr[1] += w * x1; Cr[2] += w * x2; Cr[3] += w * x3;
    }
    __syncthreads();
}

// ---------------------------------------------------------------------------
// One CTA per output site.
// K == 2 : Cholesky closed form   mean = L (L^{-1} B L^{-T})^{w2} L^T
// K != 2 : iterative Karcher mean (reference replica)
// ---------------------------------------------------------------------------
__global__ void __launch_bounds__(NTHREADS)
wfm_kernel(const float* __restrict__ x, const float* __restrict__ rw,
           float* __restrict__ out, int K, int t_out)
{
    __shared__ float sA [N * LDA];   // A -> L
    __shared__ float sW [N * LDA];   // L^{-1}   (fallback: Ms)
    __shared__ float sT1[N * LDA];   //          (fallback: Mis)
    __shared__ float sC [N * LDA];   //          (fallback: W1)
    __shared__ float sV [N * LDA];
    __shared__ float sW2[N * LDA];   // fallback only
    __shared__ float sTn[N * LDA];   // fallback only
    __shared__ float se1[N], se2[N];
    __shared__ float swt[8];

    const int tid  = threadIdx.x;
    const int bid  = blockIdx.x;
    const int band = bid % NB_BANDS;
    const int tmp  = bid / NB_BANDS;
    const int tt   = tmp % t_out;
    const int b    = tmp / t_out;

    const float* base =
        x + ((size_t)(b * T_DIM + tt) * NB_BANDS + band) * (size_t)(N * N);

    if (tid == 0) {
        float m = rw[0];
        for (int k = 1; k < K; ++k) m = fmaxf(m, rw[k]);
        float se = 0.f;
        for (int k = 0; k < K; ++k) { float e = __expf(rw[k] - m); swt[k] = e; se += e; }
        float inv = 1.0f / se;
        for (int k = 0; k < K; ++k) swt[k] *= inv;
    }
    __syncthreads();

    float* oPtr = out + ((size_t)(b * t_out + tt) * NB_BANDS + band) * (size_t)(N * N);

    if (K == 2) {
        const float* Ma = base;
        const float* Mb = base + (size_t)NB_BANDS * N * N;
        const float  w2 = swt[1];

        for (int idx = tid; idx < N * N; idx += NTHREADS)
            sA[(idx >> 5) * LDA + (idx & 31)] = Ma[idx];
        __syncthreads();

        cholesky(sA, tid);                       // sA: L (lower), junk upper
        trinv_and_cleanL(sA, sW, tid);           // sW = L^{-1}; sA upper zeroed

        mm_sg(sT1, sW, Mb, tid);                 // T1 = L^{-1} B
        mm_ss_bt(sC, sT1, sW, tid);              // C  = T1 L^{-T}

        jacobi_eigh(sC, sV, tid);                // C = V diag(mu) V^T
        if (tid < N)
            se1[tid] = __expf(w2 * __logf(fmaxf(sC[tid * LDA + tid], EPS)));
        __syncthreads();

        mm_ss(sT1, sA, sV, tid);                 // Y = L V
        recon(sC, sT1, se1, tid);                // mean = Y diag Y^T

        for (int idx = tid; idx < N * N; idx += NTHREADS)
            oPtr[idx] = sC[(idx >> 5) * LDA + (idx & 31)];
    } else {
        // ---------------- iterative fallback ----------------
        for (int idx = tid; idx < N * N; idx += NTHREADS) {
            float acc = 0.f;
            for (int k = 0; k < K; ++k)
                acc += swt[k] * base[(size_t)k * NB_BANDS * N * N + idx];
            sA[(idx >> 5) * LDA + (idx & 31)] = acc;
        }
        __syncthreads();

        for (int it = 0; it < NITERS; ++it) {
            jacobi_eigh(sA, sV, tid);
            if (tid < N) {
                float v  = fmaxf(sA[tid * LDA + tid], EPS);
                float sv = sqrtf(v);
                se1[tid] = sv;
                se2[tid] = 1.0f / sv;
            }
            __syncthreads();
            recon2(sW, sT1, sV, se1, se2, tid);  // Ms, Mis

            for (int k = 0; k < K; ++k) {
                const float* Mk = base + (size_t)k * NB_BANDS * N * N;
                mm_sg(sC, sT1, Mk, tid);
                mm_ss(sW2, sC, sT1, tid);
                jacobi_eigh(sW2, sV, tid);
                if (tid < N) se1[tid] = __logf(fmaxf(sW2[tid * LDA + tid], EPS));
                __syncthreads();
                recon_acc(sTn, sV, se1, swt[k], k == 0, tid);
            }

            jacobi_eigh(sTn, sV, tid);
            if (tid < N) se1[tid] = __expf(sTn[tid * LDA + tid]);
            __syncthreads();
            recon(sC, sV, se1, tid);
            mm_ss(sW2, sW, sC, tid);
            mm_ss(sA, sW2, sW, tid);
        }

        for (int idx = tid; idx < N * N; idx += NTHREADS)
            oPtr[idx] = sA[(idx >> 5) * LDA + (idx & 31)];
    }
}

extern "C" void kernel_launch(void* const* d_in, const int* in_sizes, int n_in,
                              void* d_out, int out_size)
{
    const float* x  = (const float*)d_in[0];
    const float* rw = (const float*)d_in[1];
    float* out = (float*)d_out;

    const int K     = in_sizes[1];        // KERNEL_SIZE (=2)
    const int t_out = T_DIM - K + 1;      // 127
    const int nblocks = B_DIM * t_out * NB_BANDS;

    wfm_kernel<<<nblocks, NTHREADS>>>(x, rw, out, K, t_out);
}

// round 5
// speedup vs baseline: 30.1604x; 1.2115x over previous
#include <cuda_runtime.h>
#include <math.h>

#define NTHREADS 256
#define N 32
#define LDA 33          // padded leading dim -> conflict-free rows AND columns
#define NSWEEP 6
#define EPS 1e-6f
#define NB_BANDS 9
#define T_DIM 128
#define B_DIM 8
#define NITERS 10

// Fast Jacobi rotation from (app, aqq, apq). MUFU-approx math, overflow-clamped.
__device__ __forceinline__ void fastrot(float app, float aqq, float apq,
                                        float& c, float& s)
{
    if (fabsf(apq) > 1e-20f) {
        float tau = __fdividef(aqq - app, 2.0f * apq);
        tau = fminf(fmaxf(tau, -1e15f), 1e15f);
        float t2  = fmaf(tau, tau, 1.0f);
        float den = fabsf(tau) + t2 * rsqrtf(t2);      // |tau| + sqrt(1+tau^2)
        float tt  = __fdividef(1.0f, den);
        tt = (tau >= 0.0f) ? tt : -tt;
        c = rsqrtf(fmaf(tt, tt, 1.0f));
        s = tt * c;
    } else { c = 1.0f; s = 0.0f; }
}

// ---------------------------------------------------------------------------
// Cyclic two-sided Jacobi eigh, warp-per-pair layout, incremental tournament
// indices (+1 mod 31 per round). 2 block barriers per round.
// On exit: diag(A) = eigenvalues, V columns = eigenvectors.
// ---------------------------------------------------------------------------
__device__ __forceinline__ void jacobi_eigh(float* A, float* V, int tid)
{
    const int wid  = tid >> 5;
    const int lane = tid & 31;
    const int lL   = lane * LDA;

    for (int idx = tid; idx < N * N; idx += NTHREADS) {
        int i = idx >> 5, j = idx & 31;
        V[i * LDA + j] = (i == j) ? 1.0f : 0.0f;
    }
    __syncthreads();

    // round-0 tournament pairs for this warp: t = wid and t = wid + 8
    int p0, q0;
    if (wid == 0) { p0 = 31; q0 = 0; }
    else          { p0 = wid; q0 = 31 - wid; }
    int p1 = wid + 8, q1 = 23 - wid;
    int pL0 = p0 * LDA, qL0 = q0 * LDA;
    int pL1 = p1 * LDA, qL1 = q1 * LDA;

    for (int round = 0; round < NSWEEP * 31; ++round) {
        float c0, s0, c1, s1;
        fastrot(A[pL0 + p0], A[qL0 + q0], A[pL0 + q0], c0, s0);
        fastrot(A[pL1 + p1], A[qL1 + q1], A[pL1 + q1], c1, s1);
        __syncwarp();

        // row update: A <- J^T A on this warp's 4 rows
        {
            float ap = A[pL0 + lane], aq = A[qL0 + lane];
            A[pL0 + lane] = c0 * ap - s0 * aq;
            A[qL0 + lane] = s0 * ap + c0 * aq;
            ap = A[pL1 + lane]; aq = A[qL1 + lane];
            A[pL1 + lane] = c1 * ap - s1 * aq;
            A[qL1 + lane] = s1 * ap + c1 * aq;
        }
        __syncthreads();

        // col update: A <- A J, V <- V J (lane = row)
        {
            float ap = A[lL + p0], aq = A[lL + q0];
            A[lL + p0] = c0 * ap - s0 * aq;
            A[lL + q0] = s0 * ap + c0 * aq;
            ap = A[lL + p1]; aq = A[lL + q1];
            A[lL + p1] = c1 * ap - s1 * aq;
            A[lL + q1] = s1 * ap + c1 * aq;
            float vp = V[lL + p0], vq = V[lL + q0];
            V[lL + p0] = c0 * vp - s0 * vq;
            V[lL + q0] = s0 * vp + c0 * vq;
            vp = V[lL + p1]; vq = V[lL + q1];
            V[lL + p1] = c1 * vp - s1 * vq;
            V[lL + q1] = s1 * vp + c1 * vq;
        }
        __syncthreads();

        // advance tournament (all indices +1 mod 31; wid0 keeps p0 = 31)
        if (wid != 0) { if (++p0 == 31) { p0 = 0; pL0 = 0; } else pL0 += LDA; }
        if (++q0 == 31) { q0 = 0; qL0 = 0; } else qL0 += LDA;
        if (++p1 == 31) { p1 = 0; pL1 = 0; } else pL1 += LDA;
        if (++q1 == 31) { q1 = 0; qL1 = 0; } else qL1 += LDA;
    }
}

// In-place Cholesky (lower). Strict upper left as junk (zeroed separately).
__device__ __forceinline__ void cholesky(float* A, int tid)
{
    for (int k = 0; k < N; ++k) {
        if (tid < 32) {
            float akk = A[k * LDA + k];
            float inv = rsqrtf(fmaxf(akk, 1e-12f));
            float v   = A[tid * LDA + k];
            float res = (tid == k) ? (akk * inv) : (v * inv);
            if (tid >= k) A[tid * LDA + k] = res;
        }
        __syncthreads();
        for (int idx = tid; idx < N * N; idx += NTHREADS) {
            int i = idx >> 5, j = idx & 31;
            if (i > k && j > k && j <= i)
                A[i * LDA + j] -= A[i * LDA + k] * A[j * LDA + k];
        }
        __syncthreads();
    }
}

// W = L^{-1} (lower-tri). Thread c owns column c.
// Threads >=32 zero the strict upper of L so it can be used in dense mm.
__device__ __forceinline__ void trinv_and_cleanL(float* L, float* W, int tid)
{
    if (tid < 32) {
        int c = tid;
        for (int k = 0; k < c; ++k) W[k * LDA + c] = 0.0f;
        for (int k = c; k < N; ++k) {
            float s = (k == c) ? 1.0f : 0.0f;
            for (int j = c; j < k; ++j)
                s -= L[k * LDA + j] * W[j * LDA + c];
            W[k * LDA + c] = s * __fdividef(1.0f, L[k * LDA + k]);
        }
    } else {
        for (int idx = tid - 32; idx < N * N; idx += (NTHREADS - 32)) {
            int i = idx >> 5, j = idx & 31;
            if (j > i) L[i * LDA + j] = 0.0f;
        }
    }
    __syncthreads();
}

// C = A @ B (both smem, LDA-padded)
__device__ __forceinline__ void mm_ss(float* C, const float* A, const float* B, int tid)
{
    int r  = tid >> 3;
    int c0 = (tid & 7) << 2;
    float a0 = 0.f, a1 = 0.f, a2 = 0.f, a3 = 0.f;
#pragma unroll 8
    for (int k = 0; k < N; ++k) {
        float a = A[r * LDA + k];
        const float* Bk = B + k * LDA + c0;
        a0 += a * Bk[0]; a1 += a * Bk[1]; a2 += a * Bk[2]; a3 += a * Bk[3];
    }
    float* Cr = C + r * LDA + c0;
    Cr[0] = a0; Cr[1] = a1; Cr[2] = a2; Cr[3] = a3;
    __syncthreads();
}

// C = A(smem) @ B(global, ld=32)
__device__ __forceinline__ void mm_sg(float* C, const float* A,
                                      const float* __restrict__ B, int tid)
{
    int r  = tid >> 3;
    int c0 = (tid & 7) << 2;
    float a0 = 0.f, a1 = 0.f, a2 = 0.f, a3 = 0.f;
#pragma unroll 8
    for (int k = 0; k < N; ++k) {
        float a = A[r * LDA + k];
        const float* Bk = B + k * N + c0;
        a0 += a * Bk[0]; a1 += a * Bk[1]; a2 += a * Bk[2]; a3 += a * Bk[3];
    }
    float* Cr = C + r * LDA + c0;
    Cr[0] = a0; Cr[1] = a1; Cr[2] = a2; Cr[3] = a3;
    __syncthreads();
}

// C = A @ B^T (both smem)
__device__ __forceinline__ void mm_ss_bt(float* C, const float* A, const float* B, int tid)
{
    int r  = tid >> 3;
    int c0 = (tid & 7) << 2;
    float a0 = 0.f, a1 = 0.f, a2 = 0.f, a3 = 0.f;
#pragma unroll 8
    for (int k = 0; k < N; ++k) {
        float a = A[r * LDA + k];
        a0 += a * B[(c0 + 0) * LDA + k];
        a1 += a * B[(c0 + 1) * LDA + k];
        a2 += a * B[(c0 + 2) * LDA + k];
        a3 += a * B[(c0 + 3) * LDA + k];
    }
    float* Cr = C + r * LDA + c0;
    Cr[0] = a0; Cr[1] = a1; Cr[2] = a2; Cr[3] = a3;
    __syncthreads();
}

// C1 = V diag(d1) V^T ; C2 = V diag(d2) V^T
__device__ __forceinline__ void recon2(float* C1, float* C2, const float* V,
                                       const float* d1, const float* d2, int tid)
{
    int r  = tid >> 3;
    int c0 = (tid & 7) << 2;
    float x0 = 0.f, x1 = 0.f, x2 = 0.f, x3 = 0.f;
    float y0 = 0.f, y1 = 0.f, y2 = 0.f, y3 = 0.f;
#pragma unroll 8
    for (int k = 0; k < N; ++k) {
        float vr = V[r * LDA + k];
        float w1 = vr * d1[k];
        float w2 = vr * d2[k];
        float v0 = V[(c0 + 0) * LDA + k];
        float v1 = V[(c0 + 1) * LDA + k];
        float v2 = V[(c0 + 2) * LDA + k];
        float v3 = V[(c0 + 3) * LDA + k];
        x0 += w1 * v0; x1 += w1 * v1; x2 += w1 * v2; x3 += w1 * v3;
        y0 += w2 * v0; y1 += w2 * v1; y2 += w2 * v2; y3 += w2 * v3;
    }
    float* C1r = C1 + r * LDA + c0;
    float* C2r = C2 + r * LDA + c0;
    C1r[0] = x0; C1r[1] = x1; C1r[2] = x2; C1r[3] = x3;
    C2r[0] = y0; C2r[1] = y1; C2r[2] = y2; C2r[3] = y3;
    __syncthreads();
}

// C = V diag(d) V^T
__device__ __forceinline__ void recon(float* C, const float* V, const float* d, int tid)
{
    int r  = tid >> 3;
    int c0 = (tid & 7) << 2;
    float x0 = 0.f, x1 = 0.f, x2 = 0.f, x3 = 0.f;
#pragma unroll 8
    for (int k = 0; k < N; ++k) {
        float w = V[r * LDA + k] * d[k];
        x0 += w * V[(c0 + 0) * LDA + k];
        x1 += w * V[(c0 + 1) * LDA + k];
        x2 += w * V[(c0 + 2) * LDA + k];
        x3 += w * V[(c0 + 3) * LDA + k];
    }
    float* Cr = C + r * LDA + c0;
    Cr[0] = x0; Cr[1] = x1; Cr[2] = x2; Cr[3] = x3;
    __syncthreads();
}

// C = (first ? 0 : C) + w * V diag(d) V^T
__device__ __forceinline__ void recon_acc(float* C, const float* V, const float* d,
                                          float w, bool first, int tid)
{
    int r  = tid >> 3;
    int c0 = (tid & 7) << 2;
    float x0 = 0.f, x1 = 0.f, x2 = 0.f, x3 = 0.f;
#pragma unroll 8
    for (int k = 0; k < N; ++k) {
        float wk = V[r * LDA + k] * d[k];
        x0 += wk * V[(c0 + 0) * LDA + k];
        x1 += wk * V[(c0 + 1) * LDA + k];
        x2 += wk * V[(c0 + 2) * LDA + k];
        x3 += wk * V[(c0 + 3) * LDA + k];
    }
    float* Cr = C + r * LDA + c0;
    if (first) {
        Cr[0] = w * x0; Cr[1] = w * x1; Cr[2] = w * x2; Cr[3] = w * x3;
    } else {
        Cr[0] += w * x0; Cr[1] += w * x1; Cr[2] += w * x2; Cr[3] += w * x3;
    }
    __syncthreads();
}

// ---------------------------------------------------------------------------
// One CTA per output site.
// K == 2 : Cholesky closed form   mean = L (L^{-1} B L^{-T})^{w2} L^T
// K != 2 : iterative Karcher mean (reference replica)
// ---------------------------------------------------------------------------
__global__ void __launch_bounds__(NTHREADS)
wfm_kernel(const float* __restrict__ x, const float* __restrict__ rw,
           float* __restrict__ out, int K, int t_out)
{
    __shared__ float sA [N * LDA];   // A -> L
    __shared__ float sW [N * LDA];   // L^{-1}   (fallback: Ms)
    __shared__ float sT1[N * LDA];   //          (fallback: Mis)
    __shared__ float sC [N * LDA];   //          (fallback: W1)
    __shared__ float sV [N * LDA];
    __shared__ float sW2[N * LDA];   // fallback only
    __shared__ float sTn[N * LDA];   // fallback only
    __shared__ float se1[N], se2[N];
    __shared__ float swt[8];

    const int tid  = threadIdx.x;
    const int bid  = blockIdx.x;
    const int band = bid % NB_BANDS;
    const int tmp  = bid / NB_BANDS;
    const int tt   = tmp % t_out;
    const int b    = tmp / t_out;

    const float* base =
        x + ((size_t)(b * T_DIM + tt) * NB_BANDS + band) * (size_t)(N * N);

    if (tid == 0) {
        float m = rw[0];
        for (int k = 1; k < K; ++k) m = fmaxf(m, rw[k]);
        float se = 0.f;
        for (int k = 0; k < K; ++k) { float e = __expf(rw[k] - m); swt[k] = e; se += e; }
        float inv = __fdividef(1.0f, se);
        for (int k = 0; k < K; ++k) swt[k] *= inv;
    }
    __syncthreads();

    float* oPtr = out + ((size_t)(b * t_out + tt) * NB_BANDS + band) * (size_t)(N * N);

    if (K == 2) {
        const float* Ma = base;
        const float* Mb = base + (size_t)NB_BANDS * N * N;
        const float  w2 = swt[1];

        for (int idx = tid; idx < N * N; idx += NTHREADS)
            sA[(idx >> 5) * LDA + (idx & 31)] = Ma[idx];
        __syncthreads();

        cholesky(sA, tid);                       // sA: L (lower), junk upper
        trinv_and_cleanL(sA, sW, tid);           // sW = L^{-1}; sA upper zeroed

        mm_sg(sT1, sW, Mb, tid);                 // T1 = L^{-1} B
        mm_ss_bt(sC, sT1, sW, tid);              // C  = T1 L^{-T}

        jacobi_eigh(sC, sV, tid);                // C = V diag(mu) V^T
        if (tid < N)
            se1[tid] = __expf(w2 * __logf(fmaxf(sC[tid * LDA + tid], EPS)));
        __syncthreads();

        mm_ss(sT1, sA, sV, tid);                 // Y = L V
        recon(sC, sT1, se1, tid);                // mean = Y diag Y^T

        for (int idx = tid; idx < N * N; idx += NTHREADS)
            oPtr[idx] = sC[(idx >> 5) * LDA + (idx & 31)];
    } else {
        // ---------------- iterative fallback ----------------
        for (int idx = tid; idx < N * N; idx += NTHREADS) {
            float acc = 0.f;
            for (int k = 0; k < K; ++k)
                acc += swt[k] * base[(size_t)k * NB_BANDS * N * N + idx];
            sA[(idx >> 5) * LDA + (idx & 31)] = acc;
        }
        __syncthreads();

        for (int it = 0; it < NITERS; ++it) {
            jacobi_eigh(sA, sV, tid);
            if (tid < N) {
                float v  = fmaxf(sA[tid * LDA + tid], EPS);
                float sv = sqrtf(v);
                se1[tid] = sv;
                se2[tid] = __fdividef(1.0f, sv);
            }
            __syncthreads();
            recon2(sW, sT1, sV, se1, se2, tid);  // Ms, Mis

            for (int k = 0; k < K; ++k) {
                const float* Mk = base + (size_t)k * NB_BANDS * N * N;
                mm_sg(sC, sT1, Mk, tid);
                mm_ss(sW2, sC, sT1, tid);
                jacobi_eigh(sW2, sV, tid);
                if (tid < N) se1[tid] = __logf(fmaxf(sW2[tid * LDA + tid], EPS));
                __syncthreads();
                recon_acc(sTn, sV, se1, swt[k], k == 0, tid);
            }

            jacobi_eigh(sTn, sV, tid);
            if (tid < N) se1[tid] = __expf(sTn[tid * LDA + tid]);
            __syncthreads();
            recon(sC, sV, se1, tid);
            mm_ss(sW2, sW, sC, tid);
            mm_ss(sA, sW2, sW, tid);
        }

        for (int idx = tid; idx < N * N; idx += NTHREADS)
            oPtr[idx] = sA[(idx >> 5) * LDA + (idx & 31)];
    }
}

extern "C" void kernel_launch(void* const* d_in, const int* in_sizes, int n_in,
                              void* d_out, int out_size)
{
    const float* x  = (const float*)d_in[0];
    const float* rw = (const float*)d_in[1];
    float* out = (float*)d_out;

    const int K     = in_sizes[1];        // KERNEL_SIZE (=2)
    const int t_out = T_DIM - K + 1;      // 127
    const int nblocks = B_DIM * t_out * NB_BANDS;

    wfm_kernel<<<nblocks, NTHREADS>>>(x, rw, out, K, t_out);
}

// round 6
// speedup vs baseline: 151.7401x; 5.0311x over previous
#include <cuda_runtime.h>
#include <math.h>

#define N 32
#define LDT 33                 // padded tile leading dim
#define WARPS_PER_CTA 4
#define NTHREADS (WARPS_PER_CTA * 32)
#define NSWEEP 6
#define EPS 1e-6f
#define NB_BANDS 9
#define T_DIM 128
#define B_DIM 8

// Jacobi rotation for implicit 2x2 [[np, bpq],[bpq, nq]]. MUFU-fast, clamped.
__device__ __forceinline__ void fastrot(float np, float nq, float bpq,
                                        float& c, float& s)
{
    if (fabsf(bpq) > 1e-20f) {
        float tau = __fdividef(nq - np, 2.0f * bpq);
        tau = fminf(fmaxf(tau, -1e15f), 1e15f);
        float t2  = fmaf(tau, tau, 1.0f);
        float den = fabsf(tau) + t2 * rsqrtf(t2);      // |tau| + sqrt(1+tau^2)
        float tt  = __fdividef(1.0f, den);
        tt = (tau >= 0.0f) ? tt : -tt;
        c = rsqrtf(fmaf(tt, tt, 1.0f));
        s = tt * c;
    } else { c = 1.0f; s = 0.0f; }
}

// Warp-cooperative in-place Cholesky (lower) of SPD 32x32 in smem. lane = row.
// Leaves junk in the strict upper triangle.
__device__ __forceinline__ void warp_chol(float* S, int lane)
{
    for (int k = 0; k < N; ++k) {
        float akk = S[k * LDT + k];                    // all lanes read
        float inv = rsqrtf(fmaxf(akk, 1e-12f));
        __syncwarp();
        float lik = 0.0f;
        if (lane >= k) {
            float v = S[lane * LDT + k];
            lik = (lane == k) ? akk * inv : v * inv;
            S[lane * LDT + k] = lik;
        }
        __syncwarp();
        if (lane > k) {
            for (int j = k + 1; j <= lane; ++j)        // S[j,k] broadcast reads
                S[lane * LDT + j] -= lik * S[j * LDT + k];
        }
        __syncwarp();
    }
}

// ---------------------------------------------------------------------------
// One WARP per output site. Whole pipeline:
//   L  = chol(A);  Lb = chol(B);  G = L^{-1} Lb   (lower-tri, lane = column)
//   one-sided Jacobi on G's columns (registers + shfl)  ->  U, lambda
//   mean = Z Z^T with z_c = L g_c * lambda_c^{(w2-1)/2}
// Requires K == 2 (KERNEL_SIZE of this problem).
// ---------------------------------------------------------------------------
__global__ void __launch_bounds__(NTHREADS)
wfm_kernel(const float* __restrict__ x, const float* __restrict__ rw,
           float* __restrict__ out, int t_out)
{
    __shared__ float tiles[WARPS_PER_CTA][2][N * LDT];

    const int lane = threadIdx.x & 31;
    const int wrp  = threadIdx.x >> 5;
    float* sA = tiles[wrp][0];                 // A -> L      (later: upper zeroed)
    float* sB = tiles[wrp][1];                 // B -> Lb -> Z

    const int site = blockIdx.x * WARPS_PER_CTA + wrp;
    const int band = site % NB_BANDS;
    const int tmp  = site / NB_BANDS;
    const int tt   = tmp % t_out;
    const int b    = tmp / t_out;

    const float* Ma = x + ((size_t)(b * T_DIM + tt) * NB_BANDS + band) * (size_t)(N * N);
    const float* Mb = Ma + (size_t)NB_BANDS * N * N;

    // softmax weight w2 (K == 2), computed redundantly per thread
    float r0 = rw[0], r1 = rw[1];
    float mx = fmaxf(r0, r1);
    float e0 = __expf(r0 - mx), e1 = __expf(r1 - mx);
    const float w2 = e1 / (e0 + e1);

    // load A, B into per-warp tiles (coalesced)
#pragma unroll
    for (int t = 0; t < N; ++t) {
        sA[t * LDT + lane] = Ma[t * N + lane];
        sB[t * LDT + lane] = Mb[t * N + lane];
    }
    __syncwarp();

    warp_chol(sA, lane);                       // sA lower = L
    warp_chol(sB, lane);                       // sB lower = Lb

    // zero strict upper of sA (so Z = L*h can be unconditional later)
#pragma unroll
    for (int j = 0; j < N; ++j)
        if (j > lane) sA[lane * LDT + j] = 0.0f;
    __syncwarp();

    // G = L^{-1} Lb, lane = column c. G is lower triangular: g[k] = 0 for k < c.
    float g[N];
#pragma unroll
    for (int k = 0; k < N; ++k) {
        float acc = sB[k * LDT + lane];        // Lb[k, c] (junk for k < c, masked)
#pragma unroll
        for (int j = 0; j < k; ++j)
            acc -= sA[k * LDT + j] * g[j];     // broadcast reads of L row k
        float val = acc * __fdividef(1.0f, sA[k * LDT + k]);
        g[k] = (k >= lane) ? val : 0.0f;
    }

    // column norm (maintained incrementally through the rotations)
    float nrm = 0.0f;
#pragma unroll
    for (int i = 0; i < N; ++i) nrm = fmaf(g[i], g[i], nrm);

    // ---------------- one-sided Jacobi on columns of G ----------------
    int rm = 0;
#pragma unroll 1
    for (int round = 0; round < NSWEEP * 31; ++round) {
        // tournament partner: fixed 31 vs rm; else (2*rm - lane) mod 31
        int partner;
        if (lane == 31) partner = rm;
        else {
            int t = 2 * rm - lane;
            if (t < 0)   t += 31;
            if (t >= 31) t -= 31;
            partner = (t == lane) ? 31 : t;
        }

        float pg[N];
#pragma unroll
        for (int i = 0; i < N; ++i)
            pg[i] = __shfl_sync(0xffffffffu, g[i], partner);

        float bpq = 0.0f;
#pragma unroll
        for (int i = 0; i < N; ++i) bpq = fmaf(g[i], pg[i], bpq);   // bit-identical in pair

        float pn  = __shfl_sync(0xffffffffu, nrm, partner);
        bool  isp = lane < partner;
        float np  = isp ? nrm : pn;
        float nq  = isp ? pn  : nrm;

        float c, s;
        fastrot(np, nq, bpq, c, s);
        float ss = isp ? -s : s;

#pragma unroll
        for (int i = 0; i < N; ++i)
            g[i] = fmaf(ss, pg[i], c * g[i]);

        // exact norm rotation identity
        nrm = c * c * nrm + s * s * pn + 2.0f * ss * c * bpq;

        if (++rm == 31) rm = 0;
    }

    // eigenvalue = final column norm (recomputed exactly); scale columns:
    // z_c = L * g_c * lambda^{(w2-1)/2}  -> mean = Z Z^T
    float lam = 0.0f;
#pragma unroll
    for (int i = 0; i < N; ++i) lam = fmaf(g[i], g[i], lam);
    lam = fmaxf(lam, EPS);
    float scale = __expf(0.5f * (w2 - 1.0f) * __logf(lam));
#pragma unroll
    for (int i = 0; i < N; ++i) g[i] *= scale;

    __syncwarp();
    // Z = L * g (store columns into sB, reuse tile)
    for (int i = 0; i < N; ++i) {
        float acc = 0.0f;
#pragma unroll
        for (int j = 0; j < N; ++j)
            acc = fmaf(sA[i * LDT + j], g[j], acc);   // upper of L is zeroed
        sB[i * LDT + lane] = acc;
    }
    __syncwarp();

    // mean[i][lane] = sum_c Z[i][c] * Z[lane][c]
    float rr[N];
#pragma unroll
    for (int c = 0; c < N; ++c) rr[c] = sB[lane * LDT + c];

    float* o = out + (size_t)site * (N * N);
    for (int i = 0; i < N; ++i) {
        float acc = 0.0f;
#pragma unroll
        for (int c = 0; c < N; ++c)
            acc = fmaf(sB[i * LDT + c], rr[c], acc);  // broadcast reads
        o[i * N + lane] = acc;                        // coalesced
    }
}

extern "C" void kernel_launch(void* const* d_in, const int* in_sizes, int n_in,
                              void* d_out, int out_size)
{
    const float* x  = (const float*)d_in[0];
    const float* rw = (const float*)d_in[1];
    float* out = (float*)d_out;

    const int K     = in_sizes[1];               // KERNEL_SIZE (= 2 for this problem)
    const int t_out = T_DIM - K + 1;             // 127
    const int sites = B_DIM * t_out * NB_BANDS;  // 9144
    const int nblocks = (sites + WARPS_PER_CTA - 1) / WARPS_PER_CTA;  // 2286

    wfm_kernel<<<nblocks, NTHREADS>>>(x, rw, out, t_out);
}

// round 7
// speedup vs baseline: 156.3592x; 1.0304x over previous
#include <cuda_runtime.h>
#include <math.h>

#define N 32
#define LDT 33                 // padded tile leading dim
#define WARPS_PER_CTA 4
#define NTHREADS (WARPS_PER_CTA * 32)
#define NSWEEP 6
#define MINSWEEP 4
#define JTOL 1e-4f
#define EPS 1e-6f
#define NB_BANDS 9
#define T_DIM 128
#define B_DIM 8

// Jacobi rotation for implicit 2x2 [[np, bpq],[bpq, nq]]. MUFU-fast, clamped.
__device__ __forceinline__ void fastrot(float np, float nq, float bpq,
                                        float& c, float& s)
{
    if (fabsf(bpq) > 1e-20f) {
        float tau = __fdividef(nq - np, 2.0f * bpq);
        tau = fminf(fmaxf(tau, -1e15f), 1e15f);
        float t2  = fmaf(tau, tau, 1.0f);
        float den = fabsf(tau) + t2 * rsqrtf(t2);      // |tau| + sqrt(1+tau^2)
        float tt  = __fdividef(1.0f, den);
        tt = (tau >= 0.0f) ? tt : -tt;
        c = rsqrtf(fmaf(tt, tt, 1.0f));                // c >= 1/sqrt(2)
        s = tt * c;
    } else { c = 1.0f; s = 0.0f; }
}

// Warp-cooperative in-place Cholesky (lower) of SPD 32x32 in smem. lane = row.
// Leaves junk in the strict upper triangle.
__device__ __forceinline__ void warp_chol(float* S, int lane)
{
    for (int k = 0; k < N; ++k) {
        float akk = S[k * LDT + k];                    // all lanes read
        float inv = rsqrtf(fmaxf(akk, 1e-12f));
        __syncwarp();
        float lik = 0.0f;
        if (lane >= k) {
            float v = S[lane * LDT + k];
            lik = (lane == k) ? akk * inv : v * inv;
            S[lane * LDT + k] = lik;
        }
        __syncwarp();
        if (lane > k) {
            for (int j = k + 1; j <= lane; ++j)        // S[j,k] broadcast reads
                S[lane * LDT + j] -= lik * S[j * LDT + k];
        }
        __syncwarp();
    }
}

// ---------------------------------------------------------------------------
// One WARP per output site:
//   L = chol(A); Lb = chol(B); G = L^{-1} Lb  (lane = column, registers)
//   one-sided Jacobi on G's columns (shfl exchange, deferred scaling,
//   per-warp early exit) -> singular system of C = G G^T
//   mean = Z Z^T with z_c = L g_c * lambda_c^{(w2-1)/2}
// Requires K == 2 (KERNEL_SIZE of this problem).
// ---------------------------------------------------------------------------
__global__ void __launch_bounds__(NTHREADS)
wfm_kernel(const float* __restrict__ x, const float* __restrict__ rw,
           float* __restrict__ out, int t_out)
{
    __shared__ float tiles[WARPS_PER_CTA][2][N * LDT];

    const int lane = threadIdx.x & 31;
    const int wrp  = threadIdx.x >> 5;
    float* sA = tiles[wrp][0];                 // A -> L  (upper zeroed later)
    float* sB = tiles[wrp][1];                 // B -> Lb -> Z

    const int site = blockIdx.x * WARPS_PER_CTA + wrp;
    const int band = site % NB_BANDS;
    const int tmp  = site / NB_BANDS;
    const int tt   = tmp % t_out;
    const int b    = tmp / t_out;

    const float* Ma = x + ((size_t)(b * T_DIM + tt) * NB_BANDS + band) * (size_t)(N * N);
    const float* Mb = Ma + (size_t)NB_BANDS * N * N;

    // softmax weight w2 (K == 2), computed redundantly per thread
    float r0 = rw[0], r1 = rw[1];
    float mx = fmaxf(r0, r1);
    float e0 = __expf(r0 - mx), e1 = __expf(r1 - mx);
    const float w2 = e1 / (e0 + e1);

    // load A, B into per-warp tiles (coalesced)
#pragma unroll
    for (int t = 0; t < N; ++t) {
        sA[t * LDT + lane] = Ma[t * N + lane];
        sB[t * LDT + lane] = Mb[t * N + lane];
    }
    __syncwarp();

    warp_chol(sA, lane);                       // sA lower = L
    warp_chol(sB, lane);                       // sB lower = Lb

    // zero strict upper of sA (so Z = L*g can be unconditional later)
#pragma unroll
    for (int j = 0; j < N; ++j)
        if (j > lane) sA[lane * LDT + j] = 0.0f;
    __syncwarp();

    // G = L^{-1} Lb, lane = column c. Lower triangular: u[k] = 0 for k < c.
    float u[N];
#pragma unroll
    for (int k = 0; k < N; ++k) {
        float acc = sB[k * LDT + lane];        // Lb[k, c] (junk for k < c, masked)
#pragma unroll
        for (int j = 0; j < k; ++j)
            acc -= sA[k * LDT + j] * u[j];     // broadcast reads of L row k
        float val = acc * __fdividef(1.0f, sA[k * LDT + k]);
        u[k] = (k >= lane) ? val : 0.0f;
    }

    float nu = 0.0f;                           // ||u||^2 (u-space)
#pragma unroll
    for (int i = 0; i < N; ++i) nu = fmaf(u[i], u[i], nu);

    // ---------------- one-sided Jacobi, deferred scaling ----------------
    // true column = alpha * u;  alpha renormalized once per sweep.
    float alpha = 1.0f;
#pragma unroll 1
    for (int sweep = 0; sweep < NSWEEP; ++sweep) {
        bool bad = false;
#pragma unroll 1
        for (int rm = 0; rm < 31; ++rm) {
            int partner;
            if (lane == 31) partner = rm;
            else {
                int t = 2 * rm - lane;
                if (t < 0)   t += 31;
                if (t >= 31) t -= 31;
                partner = (t == lane) ? 31 : t;
            }

            float pu[N];
#pragma unroll
            for (int i = 0; i < N; ++i)
                pu[i] = __shfl_sync(0xffffffffu, u[i], partner);

            float bu = 0.0f;
#pragma unroll
            for (int i = 0; i < N; ++i) bu = fmaf(u[i], pu[i], bu);  // pair-identical

            float pnu = __shfl_sync(0xffffffffu, nu, partner);
            float pal = __shfl_sync(0xffffffffu, alpha, partner);
            bool  isp = lane < partner;

            // convergence residual (scale-free, pre-rotation)
            bad |= (fabsf(bu) * rsqrtf(nu * pnu) > JTOL);

            float a2  = alpha * alpha, pa2 = pal * pal;
            float np  = isp ? a2 * nu   : pa2 * pnu;
            float nq  = isp ? pa2 * pnu : a2 * nu;
            float bpq = alpha * pal * bu;

            float c, s;
            fastrot(np, nq, bpq, c, s);
            float ss = isp ? -s : s;

            // u' = u + tfac*pu,  alpha' = c*alpha   (one FMA per element)
            float tfac = __fdividef(ss * pal, c * alpha);
#pragma unroll
            for (int i = 0; i < N; ++i) u[i] = fmaf(tfac, pu[i], u[i]);
            nu = fmaf(tfac, fmaf(tfac, pnu, 2.0f * bu), nu);
            alpha *= c;
        }

        // per-sweep renormalization (c >= 1/sqrt2 keeps alpha >= ~2e-5 here)
        nu *= alpha * alpha;
#pragma unroll
        for (int i = 0; i < N; ++i) u[i] *= alpha;
        alpha = 1.0f;

        if (sweep >= MINSWEEP - 1 && !__any_sync(0xffffffffu, bad)) break;
    }

    // eigenvalue = exact final column norm; scale columns:
    // z_c = L * u_c * lambda^{(w2-1)/2}  -> mean = Z Z^T
    float lam = 0.0f;
#pragma unroll
    for (int i = 0; i < N; ++i) lam = fmaf(u[i], u[i], lam);
    lam = fmaxf(lam, EPS);
    float scale = __expf(0.5f * (w2 - 1.0f) * __logf(lam));
#pragma unroll
    for (int i = 0; i < N; ++i) u[i] *= scale;

    __syncwarp();
    // Z = L * u (store columns into sB, reuse tile)
    for (int i = 0; i < N; ++i) {
        float acc = 0.0f;
#pragma unroll
        for (int j = 0; j < N; ++j)
            acc = fmaf(sA[i * LDT + j], u[j], acc);   // upper of L is zeroed
        sB[i * LDT + lane] = acc;
    }
    __syncwarp();

    // mean[i][lane] = sum_c Z[i][c] * Z[lane][c]
    float rr[N];
#pragma unroll
    for (int c = 0; c < N; ++c) rr[c] = sB[lane * LDT + c];

    float* o = out + (size_t)site * (N * N);
    for (int i = 0; i < N; ++i) {
        float acc = 0.0f;
#pragma unroll
        for (int c = 0; c < N; ++c)
            acc = fmaf(sB[i * LDT + c], rr[c], acc);  // broadcast reads
        o[i * N + lane] = acc;                        // coalesced
    }
}

extern "C" void kernel_launch(void* const* d_in, const int* in_sizes, int n_in,
                              void* d_out, int out_size)
{
    const float* x  = (const float*)d_in[0];
    const float* rw = (const float*)d_in[1];
    float* out = (float*)d_out;

    const int K     = in_sizes[1];               // KERNEL_SIZE (= 2 for this problem)
    const int t_out = T_DIM - K + 1;             // 127
    const int sites = B_DIM * t_out * NB_BANDS;  // 9144
    const int nblocks = (sites + WARPS_PER_CTA - 1) / WARPS_PER_CTA;  // 2286

    wfm_kernel<<<nblocks, NTHREADS>>>(x, rw, out, t_out);
}